// round 4
// baseline (speedup 1.0000x reference)
#include <cuda_runtime.h>
#include <cstdint>

// Gather kernel for NeuralPoints sampling.
// Inputs (metadata order):
//   d_in[0] points_pos   : float32 [500000, 3]
//   d_in[1] points_emb   : float32 [500000, 32]
//   d_in[2] points_color : float32 [500000, 3]
//   d_in[3] points_dir   : float32 [500000, 3]
//   d_in[4] sample_pidx  : int32   [1, 2048, 80, 8]  (n = 1,310,720)
// Output (float32, concatenated flattened tuple):
//   [0,3n)      sampled_xyz
//   [3n,35n)    sampled_emb
//   [35n,38n)   sampled_color
//   [38n,41n)   sampled_dir
//   [41n,42n)   sample_pnt_mask (1.0 / 0.0)

__global__ __launch_bounds__(256)
void neural_points_gather(const float* __restrict__ pos,
                          const float* __restrict__ emb,
                          const float* __restrict__ color,
                          const float* __restrict__ dir,
                          const int*   __restrict__ pidx,
                          float* __restrict__ out,
                          int n)
{
    const long long nl = (long long)n;
    float* __restrict__ out_xyz   = out;
    float* __restrict__ out_emb   = out + 3  * nl;
    float* __restrict__ out_color = out + 35 * nl;
    float* __restrict__ out_dir   = out + 38 * nl;
    float* __restrict__ out_mask  = out + 41 * nl;

    const float4* __restrict__ emb4     = reinterpret_cast<const float4*>(emb);
    float4*       __restrict__ out_emb4 = reinterpret_cast<float4*>(out_emb);

    const long long tid    = (long long)blockIdx.x * blockDim.x + threadIdx.x;
    const long long stride = (long long)gridDim.x * blockDim.x;

    // ---- Phase A: emb gather. 8 lanes per sample, one float4 each.
    // Each point's emb row is 32 floats = 128 B = one L2 line; 8 consecutive
    // lanes share one sample index, so the random read pulls exactly one full
    // line and the write is perfectly coalesced.
    const long long totalA = nl * 8;
    for (long long g = tid; g < totalA; g += stride) {
        const long long s = g >> 3;
        const int       j = (int)(g & 7);
        const int idx = max(__ldg(&pidx[s]), 0);
        out_emb4[s * 8 + j] = __ldg(&emb4[(long long)idx * 8 + j]);
    }

    // ---- Phase B: pos / color / dir / mask. One thread per sample.
    // Writes are contiguous across threads (12 B per thread per table).
    for (long long s = tid; s < nl; s += stride) {
        const int raw = __ldg(&pidx[s]);
        const int idx = max(raw, 0);

        const long long ib = (long long)idx * 3;
        const long long ob = s * 3;

        // Mask depends only on raw — store it before waiting on the gathers.
        out_mask[s] = (raw >= 0) ? 1.0f : 0.0f;

        // Issue all 9 independent loads up front for MLP, then store.
        const float p0 = __ldg(&pos[ib + 0]);
        const float p1 = __ldg(&pos[ib + 1]);
        const float p2 = __ldg(&pos[ib + 2]);
        const float c0 = __ldg(&color[ib + 0]);
        const float c1 = __ldg(&color[ib + 1]);
        const float c2 = __ldg(&color[ib + 2]);
        const float d0 = __ldg(&dir[ib + 0]);
        const float d1 = __ldg(&dir[ib + 1]);
        const float d2 = __ldg(&dir[ib + 2]);

        out_xyz[ob + 0]   = p0;
        out_xyz[ob + 1]   = p1;
        out_xyz[ob + 2]   = p2;
        out_color[ob + 0] = c0;
        out_color[ob + 1] = c1;
        out_color[ob + 2] = c2;
        out_dir[ob + 0]   = d0;
        out_dir[ob + 1]   = d1;
        out_dir[ob + 2]   = d2;
    }
}

extern "C" void kernel_launch(void* const* d_in, const int* in_sizes, int n_in,
                              void* d_out, int out_size)
{
    const float* pos   = (const float*)d_in[0];
    const float* emb   = (const float*)d_in[1];
    const float* color = (const float*)d_in[2];
    const float* dir   = (const float*)d_in[3];
    const int*   pidx  = (const int*)d_in[4];
    float*       out   = (float*)d_out;

    const int n = in_sizes[4];  // 1,310,720 sample indices

    // 148 SMs; give each SM many resident blocks for MLP and latency hiding.
    const int threads = 256;
    const int blocks  = 148 * 32;  // 4736 blocks, grid-stride covers n*8 work items

    neural_points_gather<<<blocks, threads>>>(pos, emb, color, dir, pidx, out, n);
}

// round 6
// speedup vs baseline: 1.0824x; 1.0824x over previous
#include <cuda_runtime.h>
#include <cstdint>

// Gather kernel for NeuralPoints sampling.
// Inputs (metadata order):
//   d_in[0] points_pos   : float32 [500000, 3]
//   d_in[1] points_emb   : float32 [500000, 32]
//   d_in[2] points_color : float32 [500000, 3]
//   d_in[3] points_dir   : float32 [500000, 3]
//   d_in[4] sample_pidx  : int32   [1, 2048, 80, 8]  (n = 1,310,720)
// Output (float32, concatenated flattened tuple):
//   [0,3n)      sampled_xyz
//   [3n,35n)    sampled_emb
//   [35n,38n)   sampled_color
//   [38n,41n)   sampled_dir
//   [41n,42n)   sample_pnt_mask (1.0 / 0.0)

__global__ __launch_bounds__(256)
void neural_points_gather(const float* __restrict__ pos,
                          const float* __restrict__ emb,
                          const float* __restrict__ color,
                          const float* __restrict__ dir,
                          const int*   __restrict__ pidx,
                          float* __restrict__ out,
                          int n)
{
    const long long nl = (long long)n;
    float* __restrict__ out_xyz   = out;
    float* __restrict__ out_emb   = out + 3  * nl;
    float* __restrict__ out_color = out + 35 * nl;
    float* __restrict__ out_dir   = out + 38 * nl;
    float* __restrict__ out_mask  = out + 41 * nl;

    const float4* __restrict__ emb4     = reinterpret_cast<const float4*>(emb);
    float4*       __restrict__ out_emb4 = reinterpret_cast<float4*>(out_emb);

    const long long tid    = (long long)blockIdx.x * blockDim.x + threadIdx.x;
    const long long stride = (long long)gridDim.x * blockDim.x;

    // ---- Phase A: emb gather. 8 lanes per sample, one float4 each.
    // Each point's emb row is 32 floats = 128 B = one L2 line; 8 consecutive
    // lanes share one sample index, so the random read pulls exactly one full
    // line (4 wavefronts per warp) and the write is perfectly coalesced.
    const long long totalA = nl * 8;
    for (long long g = tid; g < totalA; g += stride) {
        const long long s = g >> 3;
        const int       j = (int)(g & 7);
        const int idx = max(__ldg(&pidx[s]), 0);
        out_emb4[s * 8 + j] = __ldg(&emb4[(long long)idx * 8 + j]);
    }

    // ---- Phase B: pos / color / dir / mask — cooperative, 4 lanes per sample.
    // Lanes j=0..2 each move one component of pos/color/dir; lane j=3 writes
    // the mask. One warp-level LDG now touches only 8 random lines (8 samples)
    // instead of ~32, cutting L1tex wavefronts ~3-4x vs the scalar version.
    // Stores from 24 active lanes cover 96 contiguous bytes -> ~1 line each.
    const long long totalB = nl * 4;
    for (long long g = tid; g < totalB; g += stride) {
        const long long s = g >> 2;
        const int       j = (int)(g & 3);
        const int raw = __ldg(&pidx[s]);
        const int idx = max(raw, 0);

        if (j < 3) {
            const long long ib = (long long)idx * 3 + j;
            const long long ob = s * 3 + j;
            // Three independent gathers issued back-to-back for MLP.
            const float pv = __ldg(&pos[ib]);
            const float cv = __ldg(&color[ib]);
            const float dv = __ldg(&dir[ib]);
            out_xyz[ob]   = pv;
            out_color[ob] = cv;
            out_dir[ob]   = dv;
        } else {
            out_mask[s] = (raw >= 0) ? 1.0f : 0.0f;
        }
    }
}

extern "C" void kernel_launch(void* const* d_in, const int* in_sizes, int n_in,
                              void* d_out, int out_size)
{
    const float* pos   = (const float*)d_in[0];
    const float* emb   = (const float*)d_in[1];
    const float* color = (const float*)d_in[2];
    const float* dir   = (const float*)d_in[3];
    const int*   pidx  = (const int*)d_in[4];
    float*       out   = (float*)d_out;

    const int n = in_sizes[4];  // 1,310,720 sample indices

    const int threads = 256;
    const int blocks  = 148 * 32;  // 4736 blocks, grid-stride covers n*8 work items

    neural_points_gather<<<blocks, threads>>>(pos, emb, color, dir, pidx, out, n);
}